// round 11
// baseline (speedup 1.0000x reference)
#include <cuda_runtime.h>

// FlowNetC correlation on GB300 — round 11: m-half warp split (12 warps/block,
// 40 acc regs/thread) + whole-chunk fragment front-loading. ldmatrix.x4,
// banded m16n8k8 tf32 MMA, cp.async 2-stage ring.
//
// out[b, dy*21+dx, y, x] = (1/256) * sum_c in1[b,c,y,x] * in2[b,c, y+2dy-20, x+2dx-20]
//
// Prepass: both inputs -> rna-tf32 bits, layout [b][c4][y][par][xh][cc4];
// A pre-scaled by 1/256 (exact). Main: block = (dyg of 3 dy, y, b), 384 thr,
// warp = (dyl, par, mh); per warp 2 m16 tiles x 5-band n8 x 32 k8 MMAs.
// All 12 LDSM of a chunk (2 phases x {2 A + 4 B}) issue before any MMA.

#define DD      21
#define HH      96
#define WW      128
#define NCH     16                  // 16 channels per chunk
#define NDY     3
#define NTH     384                 // 12 warps

// smem (words). B: [dl 3][par 2][kh 4][u 96][4]; A: [par 2][kh 4][m 64][4]
#define B_KH    384
#define B_DP    1536
#define A_BASE  9216
#define A_PAR   1024
#define STAGE   11264
#define SMEM_BYTES (2 * STAGE * 4)  // 90112 B
#define STAGE_B (STAGE * 4)

#define ELEMS   (8 * 256 * 96 * 128)
#define CSTEP   (4 * 96 * 2 * 64 * 4)   // +4 c4 per chunk = 196608 floats

__device__ float g1t[ELEMS];   // A scratch (in1 * 1/256, tf32 bits)
__device__ float g2t[ELEMS];   // B scratch (in2, tf32 bits)

__device__ __forceinline__ unsigned cvt_tf32(float v) {
    unsigned r;
    asm("cvt.rna.tf32.f32 %0, %1;" : "=r"(r) : "f"(v));
    return r;
}
__device__ __forceinline__ void cp16(unsigned dst, const float* src) {
    asm volatile("cp.async.cg.shared.global [%0], [%1], 16;"
                 :: "r"(dst), "l"(src));
}
__device__ __forceinline__ void ldsm4(unsigned addr, unsigned& r0, unsigned& r1,
                                      unsigned& r2, unsigned& r3) {
    asm volatile("ldmatrix.sync.aligned.m8n8.x4.shared.b16 {%0,%1,%2,%3}, [%4];"
                 : "=r"(r0), "=r"(r1), "=r"(r2), "=r"(r3) : "r"(addr));
}
__device__ __forceinline__ void mma_tf32(float (&d)[4],
                                         unsigned a0, unsigned a1,
                                         unsigned a2, unsigned a3,
                                         unsigned b0, unsigned b1) {
    asm volatile(
        "mma.sync.aligned.m16n8k8.row.col.f32.tf32.tf32.f32 "
        "{%0,%1,%2,%3}, {%4,%5,%6,%7}, {%8,%9}, {%0,%1,%2,%3};"
        : "+f"(d[0]), "+f"(d[1]), "+f"(d[2]), "+f"(d[3])
        : "r"(a0), "r"(a1), "r"(a2), "r"(a3), "r"(b0), "r"(b1));
}

// ---- prepass: cvt + transpose to [b][c4][y][par][xh][cc4] (uint4 stores) ----
__global__ void __launch_bounds__(128) prepass(const float* __restrict__ s1,
                                               const float* __restrict__ s2)
{
    const int x   = threadIdx.x;
    const int y   = blockIdx.x;
    const int c4  = blockIdx.y;
    const int b   = blockIdx.z & 7;
    const bool isA = blockIdx.z >= 8;
    const size_t plane = (size_t)HH * WW;
    const float* src = (isA ? s1 : s2)
        + ((size_t)(b * 256 + c4 * 4) * HH + y) * WW + x;
    const float sc = isA ? (1.0f / 256.0f) : 1.0f;
    unsigned v0 = cvt_tf32(src[0]         * sc);
    unsigned v1 = cvt_tf32(src[plane]     * sc);
    unsigned v2 = cvt_tf32(src[2 * plane] * sc);
    unsigned v3 = cvt_tf32(src[3 * plane] * sc);
    float* dstT = isA ? g1t : g2t;
    size_t o = ((((size_t)b * 64 + c4) * HH + y) * 2 + (x & 1)) * 64 + (x >> 1);
    ((uint4*)dstT)[o] = make_uint4(v0, v1, v2, v3);
}

extern __shared__ unsigned smw[];

__global__ void __launch_bounds__(NTH, 1) corr_mma(float* __restrict__ g_out)
{
    const int b    = blockIdx.z;
    const int y    = blockIdx.y;
    const int dyg  = blockIdx.x;      // 0..6
    const int dy0  = dyg * NDY;
    const int tid  = threadIdx.x;
    const int lane = tid & 31;
    const int w    = tid >> 5;        // 0..11
    const int mh   = w & 1;           // m-half: tiles {2mh, 2mh+1}
    const int par  = (w >> 1) & 1;
    const int dyl  = w >> 2;          // 0..2
    const int g    = lane >> 2;
    const int t    = lane & 3;

    const size_t plane = (size_t)HH * WW;

    // Zero both stages once: pad u-rows and OOB-dy rows stay zero.
    for (int i = tid; i < 2 * STAGE; i += NTH) smw[i] = 0u;

    const unsigned sm0 = (unsigned)__cvta_generic_to_shared(smw);

    // ---- cp.async slots. B: 1536 16B-rows/chunk (4/thread);
    //      A: 512 (slot0 all, slot1 tid<128). ----
    unsigned boff[4], bdstB[4];
    bool     bok[4];
    #pragma unroll
    for (int q = 0; q < 4; ++q) {
        int idx = q * NTH + tid;          // 0..1535
        int u6  = idx & 63;
        int kh  = (idx >> 6) & 3;
        int pr  = (idx >> 8) & 1;
        int dl  = idx >> 9;               // 0..2
        int row2 = y + 2 * (dy0 + dl) - 20;
        bok[q]  = (row2 >= 0) && (row2 < HH);
        boff[q] = (unsigned)(((((b * 64 + kh) * HH + (bok[q] ? row2 : 0)) * 2 + pr)
                              * 64 + u6) * 4);
        bdstB[q] = sm0 + (unsigned)(((dl * 2 + pr) * B_DP + kh * B_KH
                                     + (u6 + 10) * 4) * 4);
    }
    unsigned aoff[2], adstB[2];
    #pragma unroll
    for (int q = 0; q < 2; ++q) {
        int idx = q * NTH + tid;          // valid when idx < 512
        int m   = idx & 63;
        int kh  = (idx >> 6) & 3;
        int pr  = (idx >> 8) & 1;
        aoff[q]  = (unsigned)(((((b * 64 + kh) * HH + y) * 2 + pr) * 64 + m) * 4);
        adstB[q] = sm0 + (unsigned)((A_BASE + pr * A_PAR + kh * 256 + m * 4) * 4);
    }
    const bool a1act = (tid < 128);

    // ---- ldmatrix lane bases (byte addresses, stage 0, khp=0) ----
    const unsigned bl_kh = (lane >> 3) & 1;
    const unsigned bl_u  = ((lane >> 4) << 3) + (lane & 7);
    const unsigned bLds  = sm0 + ((dyl * 2 + par) * B_DP + bl_kh * B_KH
                                  + bl_u * 4) * 4;
    const unsigned al_kh = lane >> 4;
    const unsigned al_m  = ((lane >> 3) & 1) * 8 + (lane & 7);
    const unsigned aLds  = sm0 + (A_BASE + par * A_PAR + al_kh * 256
                                  + al_m * 4) * 4;

    float acc[10][4];    // [lmt*5 + i][4]
    #pragma unroll
    for (int f = 0; f < 10; ++f)
        #pragma unroll
        for (int e = 0; e < 4; ++e) acc[f][e] = 0.0f;

    __syncthreads();   // zeroing complete before any cp.async lands

    auto issue_chunk = [&](int stg) {
        const unsigned sb = (unsigned)stg * STAGE_B;
        #pragma unroll
        for (int q = 0; q < 4; ++q) {
            if (bok[q]) cp16(bdstB[q] + sb, (const float*)g2t + boff[q]);
            boff[q] += CSTEP;
        }
        cp16(adstB[0] + sb, (const float*)g1t + aoff[0]);  aoff[0] += CSTEP;
        if (a1act) { cp16(adstB[1] + sb, (const float*)g1t + aoff[1]); aoff[1] += CSTEP; }
    };

    issue_chunk(0);
    asm volatile("cp.async.commit_group;");

    for (int k = 0; k < NCH; ++k) {
        asm volatile("cp.async.wait_group 0;");
        __syncthreads();   // chunk k visible to all; all warps done compute k-1

        if (k + 1 < NCH) {
            issue_chunk((k + 1) & 1);
            asm volatile("cp.async.commit_group;");
        }

        const unsigned sb = (unsigned)(k & 1) * STAGE_B;

        // ---- front-load ALL fragments of the chunk (both k-phases) ----
        unsigned af[2][2][4];   // [khp][lmt][reg]
        unsigned bf[2][4][4];   // [khp][jpl][reg]
        #pragma unroll
        for (int khp = 0; khp < 2; ++khp) {
            const unsigned ko_a = sb + khp * 2048;   // 2 kh rows (bytes)
            #pragma unroll
            for (int lmt = 0; lmt < 2; ++lmt)
                ldsm4(aLds + ko_a + (2 * mh + lmt) * 256,
                      af[khp][lmt][0], af[khp][lmt][1],
                      af[khp][lmt][2], af[khp][lmt][3]);
        }
        #pragma unroll
        for (int khp = 0; khp < 2; ++khp) {
            const unsigned ko_b = sb + khp * 3072;   // 2 kh rows (bytes)
            #pragma unroll
            for (int jpl = 0; jpl < 4; ++jpl)
                ldsm4(bLds + ko_b + (2 * mh + jpl) * 256,
                      bf[khp][jpl][0], bf[khp][jpl][1],
                      bf[khp][jpl][2], bf[khp][jpl][3]);
        }

        // ---- MMAs against completed fragments ----
        #pragma unroll
        for (int khp = 0; khp < 2; ++khp) {
            #pragma unroll
            for (int jpl = 0; jpl < 4; ++jpl) {
                const int jp = 2 * mh + jpl;
                const int j0 = 2 * jp;
                #pragma unroll
                for (int lmt = 0; lmt < 2; ++lmt) {
                    const int mt = 2 * mh + lmt;
                    if (2 * mt <= j0 && j0 <= 2 * mt + 4)
                        mma_tf32(acc[lmt * 5 + (j0 - 2 * mt)],
                                 af[khp][lmt][0], af[khp][lmt][1],
                                 af[khp][lmt][2], af[khp][lmt][3],
                                 bf[khp][jpl][0], bf[khp][jpl][1]);
                }
                const int j1 = j0 + 1;
                #pragma unroll
                for (int lmt = 0; lmt < 2; ++lmt) {
                    const int mt = 2 * mh + lmt;
                    if (j1 <= 10 && 2 * mt <= j1 && j1 <= 2 * mt + 4)
                        mma_tf32(acc[lmt * 5 + (j1 - 2 * mt)],
                                 af[khp][lmt][0], af[khp][lmt][1],
                                 af[khp][lmt][2], af[khp][lmt][3],
                                 bf[khp][jpl][2], bf[khp][jpl][3]);
                }
            }
        }
    }

    // ---- epilogue: band-extract + scatter stores (1/256 pre-baked in A) ----
    const int dy = dy0 + dyl;
    float* ob = g_out + ((size_t)(b * (DD * DD) + dy * DD)) * plane
                      + (size_t)y * WW + par;
    #pragma unroll
    for (int lmt = 0; lmt < 2; ++lmt) {
        const int mt = 2 * mh + lmt;
        #pragma unroll
        for (int i = 0; i < 5; ++i) {
            const int u0 = 8 * (2 * mt + i);
            const float* f = acc[lmt * 5 + i];
            #pragma unroll
            for (int e = 0; e < 4; ++e) {
                int r   = (e >= 2) ? (g + 8) : g;
                int col = 2 * t + (e & 1);
                int xh  = 16 * mt + r;
                int dx  = u0 + col - xh;
                if (dx >= 0 && dx < DD)
                    ob[(size_t)dx * plane + 2 * xh] = f[e];
            }
        }
    }
}

extern "C" void kernel_launch(void* const* d_in, const int* in_sizes, int n_in,
                              void* d_out, int out_size)
{
    (void)in_sizes; (void)n_in; (void)out_size;
    const float* in1 = (const float*)d_in[0];
    const float* in2 = (const float*)d_in[1];
    float*       out = (float*)d_out;

    // kernel 1: convert + transpose both tensors into k-contiguous scratch
    prepass<<<dim3(HH, 64, 16), 128>>>(in1, in2);

    // kernel 2: banded MMA
    cudaFuncSetAttribute(corr_mma, cudaFuncAttributeMaxDynamicSharedMemorySize,
                         SMEM_BYTES);
    dim3 grid(7, HH, 8);     // (dy-group of 3, y, b) -> 5376 blocks
    corr_mma<<<grid, NTH, SMEM_BYTES>>>(out);
}

// round 12
// speedup vs baseline: 1.5297x; 1.5297x over previous
#include <cuda_runtime.h>

// FlowNetC correlation on GB300 — round 12: R9 + depth-1 ping-pong pipeline on
// B ldmatrix fragments (hide the 29-cyc LDS latency under the previous jp's MMAs).
//
// out[b, dy*21+dx, y, x] = (1/256) * sum_c in1[b,c,y,x] * in2[b,c, y+2dy-20, x+2dx-20]
//
// Prepass: both inputs -> rna-tf32 bits in layout [b][c4][y][par][xh][cc4];
// A pre-scaled by 1/256. Main: block = (dyg of 3 dy, y, b), 6 warps = (dyl, par),
// 2 blocks/SM; per warp 4 m16 x 5-band n8 x 32 k8 mma.m16n8k8.tf32.
// Fragments via ldmatrix.x4 (conflict-free 128B lines); cp.async 4-stage ring.

#define DD      21
#define HH      96
#define WW      128
#define NCH     32
#define NDY     3
#define NTH     192

// smem (words). B: [dl 3][par 2][kh 2][u 96][4]; A: [par 2][kh 2][m 64][4]
#define B_KH    384
#define B_DP    768
#define B_WORDS 4608
#define A_BASE  4608
#define STAGE   5632
#define NSTG    4
#define SMEM_WORDS (NSTG * STAGE)   // 22528 words = 90112 B
#define STAGE_B (STAGE * 4)

#define ELEMS   (8 * 256 * 96 * 128)
#define CSTEP   (2 * 96 * 2 * 64 * 4)   // +2 c4 per chunk = 98304 floats

__device__ float g1t[ELEMS];   // A scratch (in1 * 1/256, tf32 bits)
__device__ float g2t[ELEMS];   // B scratch (in2, tf32 bits)

__device__ __forceinline__ unsigned cvt_tf32(float v) {
    unsigned r;
    asm("cvt.rna.tf32.f32 %0, %1;" : "=r"(r) : "f"(v));
    return r;
}
__device__ __forceinline__ void cp16(unsigned dst, const float* src) {
    asm volatile("cp.async.cg.shared.global [%0], [%1], 16;"
                 :: "r"(dst), "l"(src));
}
__device__ __forceinline__ void ldsm4(unsigned addr, unsigned& r0, unsigned& r1,
                                      unsigned& r2, unsigned& r3) {
    asm volatile("ldmatrix.sync.aligned.m8n8.x4.shared.b16 {%0,%1,%2,%3}, [%4];"
                 : "=r"(r0), "=r"(r1), "=r"(r2), "=r"(r3) : "r"(addr));
}
__device__ __forceinline__ void mma_tf32(float (&d)[4],
                                         unsigned a0, unsigned a1,
                                         unsigned a2, unsigned a3,
                                         unsigned b0, unsigned b1) {
    asm volatile(
        "mma.sync.aligned.m16n8k8.row.col.f32.tf32.tf32.f32 "
        "{%0,%1,%2,%3}, {%4,%5,%6,%7}, {%8,%9}, {%0,%1,%2,%3};"
        : "+f"(d[0]), "+f"(d[1]), "+f"(d[2]), "+f"(d[3])
        : "r"(a0), "r"(a1), "r"(a2), "r"(a3), "r"(b0), "r"(b1));
}

// ---- prepass: cvt + transpose to [b][c4][y][par][xh][cc4] (uint4 stores) ----
__global__ void __launch_bounds__(128) prepass(const float* __restrict__ s1,
                                               const float* __restrict__ s2)
{
    const int x   = threadIdx.x;        // 0..127
    const int y   = blockIdx.x;         // 96
    const int c4  = blockIdx.y;         // 64
    const int b   = blockIdx.z & 7;
    const bool isA = blockIdx.z >= 8;
    const size_t plane = (size_t)HH * WW;
    const float* src = (isA ? s1 : s2)
        + ((size_t)(b * 256 + c4 * 4) * HH + y) * WW + x;
    const float sc = isA ? (1.0f / 256.0f) : 1.0f;   // exact, baked into A
    unsigned v0 = cvt_tf32(src[0]         * sc);
    unsigned v1 = cvt_tf32(src[plane]     * sc);
    unsigned v2 = cvt_tf32(src[2 * plane] * sc);
    unsigned v3 = cvt_tf32(src[3 * plane] * sc);
    float* dstT = isA ? g1t : g2t;
    size_t o = ((((size_t)b * 64 + c4) * HH + y) * 2 + (x & 1)) * 64 + (x >> 1);
    ((uint4*)dstT)[o] = make_uint4(v0, v1, v2, v3);
}

extern __shared__ unsigned smw[];

__global__ void __launch_bounds__(NTH, 2) corr_mma(float* __restrict__ g_out)
{
    const int b    = blockIdx.z;
    const int y    = blockIdx.y;
    const int dyg  = blockIdx.x;      // 0..6
    const int dy0  = dyg * NDY;
    const int tid  = threadIdx.x;
    const int lane = tid & 31;
    const int w    = tid >> 5;        // 0..5 == (dyl*2 + par)
    const int par  = w & 1;
    const int g    = lane >> 2;
    const int t    = lane & 3;

    const size_t plane = (size_t)HH * WW;

    // Zero all stages once: pad u-rows (u<10, u>=74+10) and OOB-dy rows stay zero.
    for (int i = tid; i < SMEM_WORDS; i += NTH) smw[i] = 0u;

    const unsigned sm0 = (unsigned)__cvta_generic_to_shared(smw);

    // ---- cp.async slots. B: 768 16B-rows/chunk (4/thread); A: 256 (slot4 + tid<64)
    unsigned boff[4], bdstB[4];
    bool     bok[4];
    #pragma unroll
    for (int q = 0; q < 4; ++q) {
        int idx = q * NTH + tid;          // 0..767
        int u6  = idx & 63;
        int kh  = (idx >> 6) & 1;
        int pr  = (idx >> 7) & 1;
        int dl  = idx >> 8;               // 0..2
        int row2 = y + 2 * (dy0 + dl) - 20;
        bok[q]  = (row2 >= 0) && (row2 < HH);
        boff[q] = (unsigned)(((((b * 64 + kh) * HH + (bok[q] ? row2 : 0)) * 2 + pr)
                              * 64 + u6) * 4);
        bdstB[q] = sm0 + (unsigned)(((dl * 2 + pr) * B_DP + kh * B_KH
                                     + (u6 + 10) * 4) * 4);
    }
    unsigned aoff[2], adstB[2];
    #pragma unroll
    for (int q = 0; q < 2; ++q) {
        int idx = q * NTH + tid;          // valid when idx < 256
        int m   = idx & 63;
        int kh  = (idx >> 6) & 1;
        int pr  = (idx >> 7) & 1;
        aoff[q]  = (unsigned)(((((b * 64 + kh) * HH + y) * 2 + pr) * 64 + m) * 4);
        adstB[q] = sm0 + (unsigned)((A_BASE + pr * 512 + kh * 256 + m * 4) * 4);
    }
    const bool a1act = (tid < 64);

    // ---- ldmatrix lane bases (byte addresses into stage 0) ----
    const unsigned bl_kh = (lane >> 3) & 1;
    const unsigned bl_u  = ((lane >> 4) << 3) + (lane & 7);
    const unsigned bLds  = sm0 + (w * B_DP + bl_kh * B_KH + bl_u * 4) * 4;
    const unsigned al_kh = lane >> 4;
    const unsigned al_m  = ((lane >> 3) & 1) * 8 + (lane & 7);
    const unsigned aLds  = sm0 + (A_BASE + par * 512 + al_kh * 256 + al_m * 4) * 4;

    float acc[20][4];
    #pragma unroll
    for (int f = 0; f < 20; ++f)
        #pragma unroll
        for (int e = 0; e < 4; ++e) acc[f][e] = 0.0f;

    __syncthreads();   // zeroing complete before any cp.async lands

    auto issue_chunk = [&](int stg) {
        const unsigned sb = (unsigned)stg * STAGE_B;
        #pragma unroll
        for (int q = 0; q < 4; ++q) {
            if (bok[q]) cp16(bdstB[q] + sb, (const float*)g2t + boff[q]);
            boff[q] += CSTEP;
        }
        cp16(adstB[0] + sb, (const float*)g1t + aoff[0]);  aoff[0] += CSTEP;
        if (a1act) { cp16(adstB[1] + sb, (const float*)g1t + aoff[1]); aoff[1] += CSTEP; }
    };

    issue_chunk(0); asm volatile("cp.async.commit_group;");
    issue_chunk(1); asm volatile("cp.async.commit_group;");
    issue_chunk(2); asm volatile("cp.async.commit_group;");

    for (int k = 0; k < NCH; ++k) {
        asm volatile("cp.async.wait_group 2;");   // chunk k complete
        __syncthreads();  // visible to all; all warps finished compute k-1

        if (k + 3 < NCH) issue_chunk((k + 3) & 3);
        asm volatile("cp.async.commit_group;");   // uniform group counting

        const unsigned sb = (unsigned)(k & 3) * STAGE_B;

        // A fragments: 4 ldmatrix.x4 (one per m16 tile)
        unsigned a[4][4];
        #pragma unroll
        for (int mt = 0; mt < 4; ++mt)
            ldsm4(aLds + sb + mt * 256, a[mt][0], a[mt][1], a[mt][2], a[mt][3]);

        // B fragments: depth-1 ping-pong — ldsm(jp+1) issues BEFORE jp's MMAs,
        // so each LDS latency hides under the previous tile's tensor work.
        unsigned bb[2][4];
        ldsm4(bLds + sb, bb[0][0], bb[0][1], bb[0][2], bb[0][3]);
        #pragma unroll
        for (int jp = 0; jp < 6; ++jp) {
            unsigned (&cur)[4] = bb[jp & 1];
            unsigned (&nxt)[4] = bb[(jp + 1) & 1];
            if (jp < 5)
                ldsm4(bLds + sb + (jp + 1) * 256, nxt[0], nxt[1], nxt[2], nxt[3]);
            const int j0 = 2 * jp;
            #pragma unroll
            for (int mt = 0; mt < 4; ++mt)
                if (2 * mt <= j0 && j0 <= 2 * mt + 4)
                    mma_tf32(acc[mt * 5 + (j0 - 2 * mt)],
                             a[mt][0], a[mt][1], a[mt][2], a[mt][3],
                             cur[0], cur[1]);
            const int j1 = j0 + 1;
            if (j1 < 11) {
                #pragma unroll
                for (int mt = 0; mt < 4; ++mt)
                    if (2 * mt <= j1 && j1 <= 2 * mt + 4)
                        mma_tf32(acc[mt * 5 + (j1 - 2 * mt)],
                                 a[mt][0], a[mt][1], a[mt][2], a[mt][3],
                                 cur[2], cur[3]);
            }
        }
    }

    // ---- epilogue: band-extract + scatter stores (1/256 pre-baked in A) ----
    const int dy = dy0 + (w >> 1);
    float* ob = g_out + ((size_t)(b * (DD * DD) + dy * DD)) * plane
                      + (size_t)y * WW + par;
    #pragma unroll
    for (int mt = 0; mt < 4; ++mt) {
        #pragma unroll
        for (int i = 0; i < 5; ++i) {
            const int u0 = 8 * (2 * mt + i);
            const float* f = acc[mt * 5 + i];
            #pragma unroll
            for (int e = 0; e < 4; ++e) {
                int r   = (e >= 2) ? (g + 8) : g;
                int col = 2 * t + (e & 1);
                int xh  = 16 * mt + r;
                int dx  = u0 + col - xh;
                if (dx >= 0 && dx < DD)
                    ob[(size_t)dx * plane + 2 * xh] = f[e];
            }
        }
    }
}

extern "C" void kernel_launch(void* const* d_in, const int* in_sizes, int n_in,
                              void* d_out, int out_size)
{
    (void)in_sizes; (void)n_in; (void)out_size;
    const float* in1 = (const float*)d_in[0];
    const float* in2 = (const float*)d_in[1];
    float*       out = (float*)d_out;

    // kernel 1: convert + transpose both tensors into k-contiguous scratch
    prepass<<<dim3(HH, 64, 16), 128>>>(in1, in2);

    // kernel 2: banded MMA
    cudaFuncSetAttribute(corr_mma, cudaFuncAttributeMaxDynamicSharedMemorySize,
                         SMEM_WORDS * 4);
    dim3 grid(7, HH, 8);     // (dy-group of 3, y, b) -> 5376 blocks
    corr_mma<<<grid, NTH, SMEM_WORDS * 4>>>(out);
}